// round 3
// baseline (speedup 1.0000x reference)
#include <cuda_runtime.h>

#define BM 64
#define BN 64
#define BK 16

// Scratch for proj = concat(pre, wid) @ matrix : [32, 1024, 200] f32 (~26 MB)
__device__ float g_proj[32 * 1024 * 200];

// ---------------------------------------------------------------------------
// Kernel 1: proj[M=32768, N=200] = A[M, K=316] @ W[316, 200]
// A is the virtual concat of pretrained_emb (flat [32768,300]) and
// word_id_emb (flat [32768,16]).
// ---------------------------------------------------------------------------
__global__ __launch_bounds__(256) void proj_kernel(
    const float* __restrict__ P,   // [32768, 300]
    const float* __restrict__ Wd,  // [32768, 16]
    const float* __restrict__ Mt)  // [316, 200]
{
    __shared__ float As[BK][BM + 1];
    __shared__ float Bs[BK][BN + 1];

    const int m0 = blockIdx.x * BM;
    const int n0 = blockIdx.y * BN;
    const int tid = threadIdx.x;
    const int tx = tid & 15;
    const int ty = tid >> 4;

    float acc[4][4] = {};

    for (int k0 = 0; k0 < 316; k0 += BK) {
        // Load A tile: 64 rows x 16 k (consecutive threads along k, coalesced)
        #pragma unroll
        for (int i = 0; i < 4; i++) {
            int t  = tid + i * 256;
            int mm = t >> 4;
            int kk = t & 15;
            int kg = k0 + kk;
            int m  = m0 + mm;
            float v = 0.f;
            if (kg < 300)      v = P[m * 300 + kg];
            else if (kg < 316) v = Wd[m * 16 + (kg - 300)];
            As[kk][mm] = v;
        }
        // Load B tile: 16 k x 64 n (consecutive threads along n, coalesced)
        #pragma unroll
        for (int i = 0; i < 4; i++) {
            int t  = tid + i * 256;
            int kk = t >> 6;
            int nn = t & 63;
            int kg = k0 + kk;
            int n  = n0 + nn;
            Bs[kk][nn] = (kg < 316 && n < 200) ? Mt[kg * 200 + n] : 0.f;
        }
        __syncthreads();

        #pragma unroll
        for (int kk = 0; kk < BK; kk++) {
            float a[4], b[4];
            #pragma unroll
            for (int i = 0; i < 4; i++) a[i] = As[kk][ty * 4 + i];
            #pragma unroll
            for (int j = 0; j < 4; j++) b[j] = Bs[kk][tx * 4 + j];
            #pragma unroll
            for (int i = 0; i < 4; i++)
                #pragma unroll
                for (int j = 0; j < 4; j++)
                    acc[i][j] += a[i] * b[j];
        }
        __syncthreads();
    }

    #pragma unroll
    for (int i = 0; i < 4; i++) {
        int m = m0 + ty * 4 + i;
        #pragma unroll
        for (int j = 0; j < 4; j++) {
            int n = n0 + tx * 4 + j;
            if (n < 200) g_proj[m * 200 + n] = acc[i][j];
        }
    }
}

// ---------------------------------------------------------------------------
// Kernel 2: per batch b, out[b*1024+s, v] = sum_k proj[b,s,k] * roles[b,v,k]
// (M=1024, N=300, K=200), with column v==1 forced to 0.
// ---------------------------------------------------------------------------
__global__ __launch_bounds__(256) void score_kernel(
    const float* __restrict__ roles,  // [32, 300*200], [v,k] row-major per batch
    float* __restrict__ out)          // [32768, 300]
{
    __shared__ float As[BK][BM + 1];
    __shared__ float Bs[BK][BN + 1];

    const int b  = blockIdx.z;
    const int s0 = blockIdx.x * BM;
    const int v0 = blockIdx.y * BN;
    const int tid = threadIdx.x;
    const int tx = tid & 15;
    const int ty = tid >> 4;

    const float* A = g_proj + b * 1024 * 200;  // [1024, 200]
    const float* R = roles + b * 300 * 200;    // [300, 200]

    float acc[4][4] = {};

    for (int k0 = 0; k0 < 200; k0 += BK) {
        // A tile: 64 s-rows x 16 k
        #pragma unroll
        for (int i = 0; i < 4; i++) {
            int t  = tid + i * 256;
            int mm = t >> 4;
            int kk = t & 15;
            int kg = k0 + kk;
            As[kk][mm] = (kg < 200) ? A[(s0 + mm) * 200 + kg] : 0.f;
        }
        // B tile: roles is [v, k] with k contiguous -> load k-major per role row
        #pragma unroll
        for (int i = 0; i < 4; i++) {
            int t  = tid + i * 256;
            int nn = t >> 4;
            int kk = t & 15;
            int kg = k0 + kk;
            int v  = v0 + nn;
            Bs[kk][nn] = (kg < 200 && v < 300) ? R[v * 200 + kg] : 0.f;
        }
        __syncthreads();

        #pragma unroll
        for (int kk = 0; kk < BK; kk++) {
            float a[4], bb[4];
            #pragma unroll
            for (int i = 0; i < 4; i++) a[i] = As[kk][ty * 4 + i];
            #pragma unroll
            for (int j = 0; j < 4; j++) bb[j] = Bs[kk][tx * 4 + j];
            #pragma unroll
            for (int i = 0; i < 4; i++)
                #pragma unroll
                for (int j = 0; j < 4; j++)
                    acc[i][j] += a[i] * bb[j];
        }
        __syncthreads();
    }

    #pragma unroll
    for (int i = 0; i < 4; i++) {
        int s = s0 + ty * 4 + i;
        #pragma unroll
        for (int j = 0; j < 4; j++) {
            int v = v0 + tx * 4 + j;
            if (v < 300) {
                float val = (v == 1) ? 0.f : acc[i][j];
                out[(b * 1024 + s) * 300 + v] = val;
            }
        }
    }
}

extern "C" void kernel_launch(void* const* d_in, const int* in_sizes, int n_in,
                              void* d_out, int out_size) {
    const float* roles = (const float*)d_in[0];   // [32, 60000]
    const float* pre   = (const float*)d_in[1];   // [32, 1024, 300]
    const float* wid   = (const float*)d_in[2];   // [32, 1024, 16]
    const float* mat   = (const float*)d_in[3];   // [316, 200]
    float* out = (float*)d_out;                   // [32768, 300]

    // Kernel 1: M=32768 -> 512 blocks, N=200 -> 4 blocks of 64
    dim3 g1(32768 / BM, (200 + BN - 1) / BN);
    proj_kernel<<<g1, 256>>>(pre, wid, mat);

    // Kernel 2: M=1024 -> 16, N=300 -> 5, B=32
    dim3 g2(1024 / BM, (300 + BN - 1) / BN, 32);
    score_kernel<<<g2, 256>>>(roles, out);
}

// round 4
// speedup vs baseline: 1.4240x; 1.4240x over previous
#include <cuda_runtime.h>

#define BM 128
#define BN 128
#define BK 8

// Scratch for proj = concat(pre, wid) @ matrix : [32, 1024, 200] f32 (~26 MB)
__device__ float g_proj[32 * 1024 * 200];

// ---------------------------------------------------------------------------
// Kernel 1: proj[M=32768, N=200] = concat(P[.,300], Wd[.,16]) @ Mt[316, 200]
// 128x128x8 tile, 256 threads, 8x8 micro-tile, float4 smem operands.
// ---------------------------------------------------------------------------
__global__ __launch_bounds__(256) void proj_kernel(
    const float* __restrict__ P,   // [32768, 300]
    const float* __restrict__ Wd,  // [32768, 16]
    const float* __restrict__ Mt)  // [316, 200]
{
    __shared__ __align__(16) float As[BK][BM + 4];
    __shared__ __align__(16) float Bs[BK][BN + 4];

    const int m0 = blockIdx.x * BM;
    const int n0 = blockIdx.y * BN;
    const int tid = threadIdx.x;
    const int tx = tid & 15;          // 0..15 -> 8 columns each
    const int ty = tid >> 4;          // 0..15 -> 8 rows each

    // A-tile loader mapping: 256 threads -> 128 rows x 2 float4 along k
    const int la_m  = tid >> 1;           // 0..127
    const int la_k4 = (tid & 1) * 4;      // 0 or 4
    // B-tile loader mapping: 8 k-rows x 32 float4 along n
    const int lb_k  = tid >> 5;           // 0..7
    const int lb_n  = (tid & 31) * 4;     // 0..124

    float acc[8][8] = {};

    for (int k0 = 0; k0 < 316; k0 += BK) {
        // ---- load A tile (virtual concat), float4 along k ----
        {
            int kg = k0 + la_k4;
            int m  = m0 + la_m;
            float4 v = make_float4(0.f, 0.f, 0.f, 0.f);
            if (kg + 3 < 300) {
                v = *reinterpret_cast<const float4*>(&P[m * 300 + kg]);
            } else if (kg >= 300 && kg + 3 < 316) {
                v = *reinterpret_cast<const float4*>(&Wd[m * 16 + (kg - 300)]);
            }
            As[la_k4 + 0][la_m] = v.x;
            As[la_k4 + 1][la_m] = v.y;
            As[la_k4 + 2][la_m] = v.z;
            As[la_k4 + 3][la_m] = v.w;
        }
        // ---- load B tile from Mt, float4 along n ----
        {
            int kg = k0 + lb_k;
            int n  = n0 + lb_n;
            float4 v = make_float4(0.f, 0.f, 0.f, 0.f);
            if (kg < 316 && n < 200)  // 200 % 4 == 0 -> full float4 in range
                v = *reinterpret_cast<const float4*>(&Mt[kg * 200 + n]);
            *reinterpret_cast<float4*>(&Bs[lb_k][lb_n]) = v;
        }
        __syncthreads();

        #pragma unroll
        for (int kk = 0; kk < BK; kk++) {
            float4 a0 = *reinterpret_cast<const float4*>(&As[kk][ty * 8]);
            float4 a1 = *reinterpret_cast<const float4*>(&As[kk][ty * 8 + 4]);
            float4 b0 = *reinterpret_cast<const float4*>(&Bs[kk][tx * 8]);
            float4 b1 = *reinterpret_cast<const float4*>(&Bs[kk][tx * 8 + 4]);
            float a[8] = {a0.x, a0.y, a0.z, a0.w, a1.x, a1.y, a1.z, a1.w};
            float b[8] = {b0.x, b0.y, b0.z, b0.w, b1.x, b1.y, b1.z, b1.w};
            #pragma unroll
            for (int i = 0; i < 8; i++)
                #pragma unroll
                for (int j = 0; j < 8; j++)
                    acc[i][j] += a[i] * b[j];
        }
        __syncthreads();
    }

    // ---- epilogue: float4 stores, guard n < 200 ----
    #pragma unroll
    for (int i = 0; i < 8; i++) {
        int m = m0 + ty * 8 + i;
        #pragma unroll
        for (int j4 = 0; j4 < 2; j4++) {
            int n = n0 + tx * 8 + j4 * 4;
            if (n < 200) {
                float4 v = make_float4(acc[i][j4 * 4 + 0], acc[i][j4 * 4 + 1],
                                       acc[i][j4 * 4 + 2], acc[i][j4 * 4 + 3]);
                *reinterpret_cast<float4*>(&g_proj[m * 200 + n]) = v;
            }
        }
    }
}

// ---------------------------------------------------------------------------
// Kernel 2: per batch b, out[b*1024+s, v] = sum_k proj[b,s,k] * roles[b,v,k]
// M=1024, N=300, K=200; column v==1 zeroed. Same 128x128x8 scheme.
// ---------------------------------------------------------------------------
__global__ __launch_bounds__(256) void score_kernel(
    const float* __restrict__ roles,  // [32][300][200] (v,k)
    float* __restrict__ out)          // [32768, 300]
{
    __shared__ __align__(16) float As[BK][BM + 4];
    __shared__ __align__(16) float Bs[BK][BN + 4];

    const int b  = blockIdx.z;
    const int s0 = blockIdx.x * BM;
    const int v0 = blockIdx.y * BN;
    const int tid = threadIdx.x;
    const int tx = tid & 15;
    const int ty = tid >> 4;

    const int la_m  = tid >> 1;
    const int la_k4 = (tid & 1) * 4;
    const int lb_v  = tid >> 1;           // 0..127 (role row within tile)
    const int lb_k4 = (tid & 1) * 4;

    const float* A = g_proj + b * 1024 * 200;  // [1024, 200]
    const float* R = roles + b * 300 * 200;    // [300, 200]

    float acc[8][8] = {};

    for (int k0 = 0; k0 < 200; k0 += BK) {   // 25 exact iterations
        // ---- A tile: [s, k] -> As[k][s], float4 along k then scatter ----
        {
            int kg = k0 + la_k4;             // always < 200
            float4 v = *reinterpret_cast<const float4*>(&A[(s0 + la_m) * 200 + kg]);
            As[la_k4 + 0][la_m] = v.x;
            As[la_k4 + 1][la_m] = v.y;
            As[la_k4 + 2][la_m] = v.z;
            As[la_k4 + 3][la_m] = v.w;
        }
        // ---- B tile: roles [v, k] -> Bs[k][v], float4 along k then scatter ----
        {
            int v  = v0 + lb_v;
            int kg = k0 + lb_k4;             // always < 200
            float4 val = make_float4(0.f, 0.f, 0.f, 0.f);
            if (v < 300)
                val = *reinterpret_cast<const float4*>(&R[v * 200 + kg]);
            Bs[lb_k4 + 0][lb_v] = val.x;
            Bs[lb_k4 + 1][lb_v] = val.y;
            Bs[lb_k4 + 2][lb_v] = val.z;
            Bs[lb_k4 + 3][lb_v] = val.w;
        }
        __syncthreads();

        #pragma unroll
        for (int kk = 0; kk < BK; kk++) {
            float4 a0 = *reinterpret_cast<const float4*>(&As[kk][ty * 8]);
            float4 a1 = *reinterpret_cast<const float4*>(&As[kk][ty * 8 + 4]);
            float4 b0 = *reinterpret_cast<const float4*>(&Bs[kk][tx * 8]);
            float4 b1 = *reinterpret_cast<const float4*>(&Bs[kk][tx * 8 + 4]);
            float a[8] = {a0.x, a0.y, a0.z, a0.w, a1.x, a1.y, a1.z, a1.w};
            float bb[8] = {b0.x, b0.y, b0.z, b0.w, b1.x, b1.y, b1.z, b1.w};
            #pragma unroll
            for (int i = 0; i < 8; i++)
                #pragma unroll
                for (int j = 0; j < 8; j++)
                    acc[i][j] += a[i] * bb[j];
        }
        __syncthreads();
    }

    // ---- epilogue: zero column v==1, float4 stores, guard v < 300 ----
    #pragma unroll
    for (int i = 0; i < 8; i++) {
        int s = s0 + ty * 8 + i;
        float* orow = &out[(b * 1024 + s) * 300];
        #pragma unroll
        for (int j4 = 0; j4 < 2; j4++) {
            int v = v0 + tx * 8 + j4 * 4;
            if (v < 300) {
                float4 val = make_float4(acc[i][j4 * 4 + 0], acc[i][j4 * 4 + 1],
                                         acc[i][j4 * 4 + 2], acc[i][j4 * 4 + 3]);
                if (v == 0) val.y = 0.f;   // column 1 lives at lane .y of the v=0 float4
                *reinterpret_cast<float4*>(&orow[v]) = val;
            }
        }
    }
}

extern "C" void kernel_launch(void* const* d_in, const int* in_sizes, int n_in,
                              void* d_out, int out_size) {
    const float* roles = (const float*)d_in[0];   // [32, 60000]
    const float* pre   = (const float*)d_in[1];   // [32, 1024, 300]
    const float* wid   = (const float*)d_in[2];   // [32, 1024, 16]
    const float* mat   = (const float*)d_in[3];   // [316, 200]
    float* out = (float*)d_out;                   // [32768, 300]

    // Kernel 1: M=32768 -> 256 blocks, N=200 -> 2 blocks of 128
    dim3 g1(32768 / BM, (200 + BN - 1) / BN);
    proj_kernel<<<g1, 256>>>(pre, wid, mat);

    // Kernel 2: M=1024 -> 8, N=300 -> 3, B=32
    dim3 g2(1024 / BM, (300 + BN - 1) / BN, 32);
    score_kernel<<<g2, 256>>>(roles, out);
}

// round 5
// speedup vs baseline: 2.9139x; 2.0463x over previous
#include <cuda_runtime.h>
#include <cstdint>

// Scratch for proj = concat(pre, wid) @ matrix : [32, 1024, 200] f32 (~26 MB)
__device__ float g_proj[32 * 1024 * 200];

#define BM 128
#define BN 128
#define BK 16
#define SA 20   // As row stride (16 + 4 pad): conflict-free a-frag loads
#define SB 20   // Bs row stride for n-major layout (kernel 2)
#define SB1 132 // Bs row stride for k-major layout (kernel 1)

__device__ __forceinline__ uint32_t f2tf32(float f) {
    uint32_t u;
    asm("cvt.rna.tf32.f32 %0, %1;" : "=r"(u) : "f"(f));
    return u;
}

__device__ __forceinline__ void mma_tf32(float c[4],
                                         uint32_t a0, uint32_t a1, uint32_t a2, uint32_t a3,
                                         uint32_t b0, uint32_t b1) {
    asm volatile(
        "mma.sync.aligned.m16n8k8.row.col.f32.tf32.tf32.f32 "
        "{%0,%1,%2,%3}, {%4,%5,%6,%7}, {%8,%9}, {%0,%1,%2,%3};"
        : "+f"(c[0]), "+f"(c[1]), "+f"(c[2]), "+f"(c[3])
        : "r"(a0), "r"(a1), "r"(a2), "r"(a3), "r"(b0), "r"(b1));
}

// ---------------------------------------------------------------------------
// Kernel 1: proj[32768, 200] = concat(P[.,300], Wd[.,16]) @ Mt[316, 200]
// As: [m][k] stride SA. Bs: [k][n] stride SB1 (Mt is k-major; no transpose).
// ---------------------------------------------------------------------------
__global__ __launch_bounds__(256) void proj_kernel(
    const float* __restrict__ P,
    const float* __restrict__ Wd,
    const float* __restrict__ Mt)
{
    __shared__ __align__(16) uint32_t As[BM * SA];
    __shared__ __align__(16) uint32_t Bs[BK * SB1];

    const int m0 = blockIdx.x * BM;
    const int n0 = blockIdx.y * BN;
    const int tid  = threadIdx.x;
    const int lane = tid & 31;
    const int warp = tid >> 5;
    const int warpM = warp >> 2;           // 0..1  -> 64 rows
    const int warpN = warp & 3;            // 0..3  -> 32 cols
    const int grp = lane >> 2;             // 0..7
    const int tig = lane & 3;              // 0..3

    // loaders
    const int la_m   = tid >> 1;           // 0..127
    const int la_k8  = (tid & 1) * 8;      // 0 or 8
    const int lb_k   = tid >> 4;           // 0..15
    const int lb_n8  = (tid & 15) * 8;     // 0..120

    float acc[4][4][4] = {};

    for (int k0 = 0; k0 < 316; k0 += BK) {
        // ---- A tile (virtual concat): two float4 per thread along k ----
        #pragma unroll
        for (int h = 0; h < 2; h++) {
            int koff = la_k8 + h * 4;
            int kg = k0 + koff;
            int m  = m0 + la_m;
            float4 v = make_float4(0.f, 0.f, 0.f, 0.f);
            if (kg < 300)       v = *reinterpret_cast<const float4*>(&P[m * 300 + kg]);
            else if (kg < 316)  v = *reinterpret_cast<const float4*>(&Wd[m * 16 + (kg - 300)]);
            uint32_t* dst = &As[la_m * SA + koff];
            dst[0] = f2tf32(v.x); dst[1] = f2tf32(v.y);
            dst[2] = f2tf32(v.z); dst[3] = f2tf32(v.w);
        }
        // ---- B tile from Mt [k][n]: two float4 per thread along n ----
        #pragma unroll
        for (int h = 0; h < 2; h++) {
            int n  = n0 + lb_n8 + h * 4;
            int kg = k0 + lb_k;
            float4 v = make_float4(0.f, 0.f, 0.f, 0.f);
            if (kg < 316 && n < 200)
                v = *reinterpret_cast<const float4*>(&Mt[kg * 200 + n]);
            uint32_t* dst = &Bs[lb_k * SB1 + lb_n8 + h * 4];
            dst[0] = f2tf32(v.x); dst[1] = f2tf32(v.y);
            dst[2] = f2tf32(v.z); dst[3] = f2tf32(v.w);
        }
        __syncthreads();

        #pragma unroll
        for (int ks = 0; ks < 2; ks++) {
            const int kb = ks * 8;
            uint32_t af[4][4], bf[4][2];
            #pragma unroll
            for (int mi = 0; mi < 4; mi++) {
                int r = warpM * 64 + mi * 16 + grp;
                af[mi][0] = As[(r    ) * SA + kb + tig    ];
                af[mi][1] = As[(r + 8) * SA + kb + tig    ];
                af[mi][2] = As[(r    ) * SA + kb + tig + 4];
                af[mi][3] = As[(r + 8) * SA + kb + tig + 4];
            }
            #pragma unroll
            for (int ni = 0; ni < 4; ni++) {
                int n = warpN * 32 + ni * 8 + grp;
                bf[ni][0] = Bs[(kb + tig    ) * SB1 + n];
                bf[ni][1] = Bs[(kb + tig + 4) * SB1 + n];
            }
            #pragma unroll
            for (int mi = 0; mi < 4; mi++)
                #pragma unroll
                for (int ni = 0; ni < 4; ni++)
                    mma_tf32(acc[mi][ni], af[mi][0], af[mi][1], af[mi][2], af[mi][3],
                             bf[ni][0], bf[ni][1]);
        }
        __syncthreads();
    }

    // ---- epilogue: float2 stores (c0,c1) / (c2,c3), guard n<200 ----
    #pragma unroll
    for (int mi = 0; mi < 4; mi++) {
        #pragma unroll
        for (int ni = 0; ni < 4; ni++) {
            int n = n0 + warpN * 32 + ni * 8 + 2 * tig;
            if (n < 200) {
                int r0 = m0 + warpM * 64 + mi * 16 + grp;
                *reinterpret_cast<float2*>(&g_proj[r0 * 200 + n]) =
                    make_float2(acc[mi][ni][0], acc[mi][ni][1]);
                *reinterpret_cast<float2*>(&g_proj[(r0 + 8) * 200 + n]) =
                    make_float2(acc[mi][ni][2], acc[mi][ni][3]);
            }
        }
    }
}

// ---------------------------------------------------------------------------
// Kernel 2: out[b*1024+s, v] = sum_k proj[b,s,k] * roles[b,v,k], col v==1 = 0
// As: [s][k] stride SA. Bs: [v][k] stride SB (both operands k-major rows).
// ---------------------------------------------------------------------------
__global__ __launch_bounds__(256) void score_kernel(
    const float* __restrict__ roles,
    float* __restrict__ out)
{
    __shared__ __align__(16) uint32_t As[BM * SA];
    __shared__ __align__(16) uint32_t Bs[BN * SB];

    const int b  = blockIdx.z;
    const int s0 = blockIdx.x * BM;
    const int v0 = blockIdx.y * BN;
    const int tid  = threadIdx.x;
    const int lane = tid & 31;
    const int warp = tid >> 5;
    const int warpM = warp >> 2;
    const int warpN = warp & 3;
    const int grp = lane >> 2;
    const int tig = lane & 3;

    const int l_r   = tid >> 1;            // 0..127
    const int l_k8  = (tid & 1) * 8;

    const float* A = g_proj + b * 1024 * 200;
    const float* R = roles + b * 300 * 200;

    float acc[4][4][4] = {};

    for (int k0 = 0; k0 < 200; k0 += BK) {   // 13 iters, tail zero-filled
        #pragma unroll
        for (int h = 0; h < 2; h++) {
            int koff = l_k8 + h * 4;
            int kg = k0 + koff;
            // A tile
            {
                float4 v = make_float4(0.f, 0.f, 0.f, 0.f);
                if (kg < 200)
                    v = *reinterpret_cast<const float4*>(&A[(s0 + l_r) * 200 + kg]);
                uint32_t* dst = &As[l_r * SA + koff];
                dst[0] = f2tf32(v.x); dst[1] = f2tf32(v.y);
                dst[2] = f2tf32(v.z); dst[3] = f2tf32(v.w);
            }
            // B tile
            {
                int v_ = v0 + l_r;
                float4 v = make_float4(0.f, 0.f, 0.f, 0.f);
                if (kg < 200 && v_ < 300)
                    v = *reinterpret_cast<const float4*>(&R[v_ * 200 + kg]);
                uint32_t* dst = &Bs[l_r * SB + koff];
                dst[0] = f2tf32(v.x); dst[1] = f2tf32(v.y);
                dst[2] = f2tf32(v.z); dst[3] = f2tf32(v.w);
            }
        }
        __syncthreads();

        #pragma unroll
        for (int ks = 0; ks < 2; ks++) {
            const int kb = ks * 8;
            uint32_t af[4][4], bf[4][2];
            #pragma unroll
            for (int mi = 0; mi < 4; mi++) {
                int r = warpM * 64 + mi * 16 + grp;
                af[mi][0] = As[(r    ) * SA + kb + tig    ];
                af[mi][1] = As[(r + 8) * SA + kb + tig    ];
                af[mi][2] = As[(r    ) * SA + kb + tig + 4];
                af[mi][3] = As[(r + 8) * SA + kb + tig + 4];
            }
            #pragma unroll
            for (int ni = 0; ni < 4; ni++) {
                int n = warpN * 32 + ni * 8 + grp;
                bf[ni][0] = Bs[n * SB + kb + tig    ];
                bf[ni][1] = Bs[n * SB + kb + tig + 4];
            }
            #pragma unroll
            for (int mi = 0; mi < 4; mi++)
                #pragma unroll
                for (int ni = 0; ni < 4; ni++)
                    mma_tf32(acc[mi][ni], af[mi][0], af[mi][1], af[mi][2], af[mi][3],
                             bf[ni][0], bf[ni][1]);
        }
        __syncthreads();
    }

    // ---- epilogue: zero col v==1, float2 stores, guard v<300 ----
    #pragma unroll
    for (int mi = 0; mi < 4; mi++) {
        #pragma unroll
        for (int ni = 0; ni < 4; ni++) {
            int v = v0 + warpN * 32 + ni * 8 + 2 * tig;
            if (v < 300) {
                float2 lo = make_float2(acc[mi][ni][0], acc[mi][ni][1]);
                float2 hi = make_float2(acc[mi][ni][2], acc[mi][ni][3]);
                if (v == 0) { lo.y = 0.f; hi.y = 0.f; }  // column 1
                int s = s0 + warpM * 64 + mi * 16 + grp;
                *reinterpret_cast<float2*>(&out[(b * 1024 + s) * 300 + v]) = lo;
                *reinterpret_cast<float2*>(&out[(b * 1024 + s + 8) * 300 + v]) = hi;
            }
        }
    }
}

extern "C" void kernel_launch(void* const* d_in, const int* in_sizes, int n_in,
                              void* d_out, int out_size) {
    const float* roles = (const float*)d_in[0];   // [32, 60000]
    const float* pre   = (const float*)d_in[1];   // [32, 1024, 300]
    const float* wid   = (const float*)d_in[2];   // [32, 1024, 16]
    const float* mat   = (const float*)d_in[3];   // [316, 200]
    float* out = (float*)d_out;                   // [32768, 300]

    dim3 g1(32768 / BM, (200 + BN - 1) / BN);     // 256 x 2
    proj_kernel<<<g1, 256>>>(pre, wid, mat);

    dim3 g2(1024 / BM, (300 + BN - 1) / BN, 32);  // 8 x 3 x 32
    score_kernel<<<g2, 256>>>(roles, out);
}